// round 6
// baseline (speedup 1.0000x reference)
#include <cuda_runtime.h>

#define T_STEPS 2048
#define BATCH   256
#define DIN     128
#define NG      16      // scratch layout k = g*4 + u
#define RDEPTH  4

// Scratch: x-part projections (+bias+theta folded), layout [t][b][g*4+u]
__device__ float g_xproj[(T_STEPS + RDEPTH) * BATCH * NG];

// ---------------------------------------------------------------------------
// Kernel 1: fused 4-gate projection
// ---------------------------------------------------------------------------
#define TILE_ROWS    64
#define PROJ_THREADS 256

__global__ __launch_bounds__(PROJ_THREADS)
void proj_kernel(const float* __restrict__ x,
                 const float* __restrict__ Wf, const float* __restrict__ bf, const float* __restrict__ thf,
                 const float* __restrict__ Wi, const float* __restrict__ bi, const float* __restrict__ thi,
                 const float* __restrict__ Wu, const float* __restrict__ bu, const float* __restrict__ thu,
                 const float* __restrict__ Wo, const float* __restrict__ bo, const float* __restrict__ tho)
{
    __shared__ float xs[TILE_ROWS][132];
    __shared__ float ws[DIN][NG];          // ws[j][g*4+u]
    __shared__ float bt[NG];

    const int tid = threadIdx.x;
    const long rowBase = (long)blockIdx.x * TILE_ROWS;

    const float4* x4 = (const float4*)x + rowBase * (DIN / 4);
    #pragma unroll
    for (int i = tid; i < TILE_ROWS * (DIN / 4); i += PROJ_THREADS) {
        float4 v = x4[i];
        int row = i >> 5;
        int c4  = i & 31;
        *(float4*)&xs[row][c4 * 4] = v;
    }
    // stage W: k = g*4 + u
    for (int i = tid; i < DIN * NG; i += PROJ_THREADS) {
        int j = i >> 4, k = i & 15;
        int g = k >> 2, u = k & 3;
        const float* W = (g == 0) ? Wf : (g == 1) ? Wi : (g == 2) ? Wu : Wo;
        ws[j][k] = W[j * 4 + u];
    }
    if (tid < NG) {
        int g = tid >> 2, u = tid & 3;
        const float* b  = (g == 0) ? bf  : (g == 1) ? bi  : (g == 2) ? bu  : bo;
        const float* th = (g == 0) ? thf : (g == 1) ? thi : (g == 2) ? thu : tho;
        bt[tid] = b[u] + th[u];
    }
    __syncthreads();

    const int r  = tid & (TILE_ROWS - 1);
    const int kg = tid >> 6;               // gate under new layout
    float a0 = 0.f, a1 = 0.f, a2 = 0.f, a3 = 0.f;

    #pragma unroll
    for (int jj = 0; jj < DIN / 4; jj++) {
        float4 xv = *(const float4*)&xs[r][jj * 4];
        float4 w0 = *(const float4*)&ws[jj * 4 + 0][kg * 4];
        float4 w1 = *(const float4*)&ws[jj * 4 + 1][kg * 4];
        float4 w2 = *(const float4*)&ws[jj * 4 + 2][kg * 4];
        float4 w3 = *(const float4*)&ws[jj * 4 + 3][kg * 4];
        a0 = fmaf(xv.x, w0.x, fmaf(xv.y, w1.x, fmaf(xv.z, w2.x, fmaf(xv.w, w3.x, a0))));
        a1 = fmaf(xv.x, w0.y, fmaf(xv.y, w1.y, fmaf(xv.z, w2.y, fmaf(xv.w, w3.y, a1))));
        a2 = fmaf(xv.x, w0.z, fmaf(xv.y, w1.z, fmaf(xv.z, w2.z, fmaf(xv.w, w3.z, a2))));
        a3 = fmaf(xv.x, w0.w, fmaf(xv.y, w1.w, fmaf(xv.z, w2.w, fmaf(xv.w, w3.w, a3))));
    }
    float4 o;
    o.x = a0 + bt[kg * 4 + 0];
    o.y = a1 + bt[kg * 4 + 1];
    o.z = a2 + bt[kg * 4 + 2];
    o.w = a3 + bt[kg * 4 + 3];
    *(float4*)&g_xproj[(rowBase + r) * NG + kg * 4] = o;
}

// ---------------------------------------------------------------------------
// Kernel 2: recurrence; 16 lanes per batch element, lane = (gate g, unit u)
// ---------------------------------------------------------------------------
__device__ __forceinline__ float sigp(float xv) {
    float x2 = xv * xv;
    float t = fmaf(x2, 2.135765e-5f, -2.1081349e-4f);
    t = fmaf(x2, t, 2.0833333e-3f);
    t = fmaf(x2, t, -2.0833333e-2f);
    t = fmaf(x2, t, 0.25f);
    return fmaf(xv, t, 0.5f);
}
// tanh via continued-fraction rational, err < ~1e-5 for |x| <= 2.2; 1 MUFU.RCP
__device__ __forceinline__ float tanh_cf_fast(float xv) {
    float t = xv * xv;
    float num = fmaf(t, fmaf(t, 21.0f, 1260.0f), 10395.0f);
    float den = fmaf(t, fmaf(t, fmaf(t, 1.0f, 210.0f), 4725.0f), 10395.0f);
    return __fdividef(xv * num, den);
}

#define FULLMASK 0xffffffffu

__global__ __launch_bounds__(32)
void recur_kernel(const float* __restrict__ Wf, const float* __restrict__ Wi,
                  const float* __restrict__ Wu, const float* __restrict__ Wo,
                  float* __restrict__ out)
{
    const int lane = threadIdx.x;
    const int half = lane >> 4;            // 0/1 -> which batch element of this warp
    const int lsub = lane & 15;            // position within the 16-lane group
    const int g    = lsub >> 2;            // gate owned by this lane
    const int u    = lane & 3;             // unit owned by this lane
    const int b    = blockIdx.x * 2 + half;

    // Whl[m] = W_{gate g}[(128+m)*4 + u]
    const float* Wg = (g == 0) ? Wf : (g == 1) ? Wi : (g == 2) ? Wu : Wo;
    const float w0 = Wg[(128 + 0) * 4 + u];
    const float w1 = Wg[(128 + 1) * 4 + u];
    const float w2 = Wg[(128 + 2) * 4 + u];
    const float w3 = Wg[(128 + 3) * 4 + u];

    const bool ge1 = (u >= 1);
    const bool ge2 = (u >= 2);
    const bool ge3 = (u >= 3);
    const bool isTanhGate = (g == 2);
    const bool isStore    = (g == 0);      // f-quad lanes own c and emit h

    float h0 = 0.f, h1 = 0.f, h2 = 0.f, h3 = 0.f;
    float c  = 0.f;
    float huK = 0.f;                       // last h_u (valid on store lanes)

    // per-lane xproj stream: element (t*BATCH + b)*16 + lsub ; 128B/warp/step coalesced
    const float* xp = g_xproj + ((size_t)b * NG + lsub);
    float buf[RDEPTH];
    #pragma unroll
    for (int d = 0; d < RDEPTH; d++)
        buf[d] = xp[(size_t)d * (BATCH * NG)];

    #pragma unroll 2
    for (int t = 0; t < T_STEPS; t++) {
        const int slot = t & (RDEPTH - 1);
        float zx = buf[slot];
        buf[slot] = xp[(size_t)(t + RDEPTH) * (BATCH * NG)];   // over-allocated

        // z = zx + h . w  (tree), then cos
        float p01 = fmaf(h1, w1, h0 * w0);
        float p23 = fmaf(h3, w3, h2 * w2);
        float q = __cosf(zx + (p01 + p23));

        // branch-free prefix product across the unit-quad (width 4)
        float s0 = __shfl_sync(FULLMASK, q, 0, 4);
        float s1 = __shfl_sync(FULLMASK, q, 1, 4);
        float s2 = __shfl_sync(FULLMASK, q, 2, 4);
        float P = (q * (ge1 ? s0 : 1.0f)) * ((ge2 ? s1 : 1.0f) * (ge3 ? s2 : 1.0f));

        // activation: tanh for the update gate, sigmoid otherwise (no divergence)
        float act = isTanhGate ? tanh_cf_fast(P) : sigp(P);

        // gather i, g, o activations onto the f-quad lanes (width-16 segments)
        float iv = __shfl_sync(FULLMASK, act,  4 + u, 16);
        float gv = __shfl_sync(FULLMASK, act,  8 + u, 16);
        float ov = __shfl_sync(FULLMASK, act, 12 + u, 16);

        // cell + hidden update (meaningful on store lanes; bounded garbage elsewhere)
        c = fmaf(act, c, iv * gv);         // act == f on store lanes
        float hu = ov * tanh_cf_fast(c);
        huK = hu;

        if (isStore)
            out[((size_t)t * BATCH + b) * 4 + u] = hu;

        // broadcast h within the 16-lane segment (h lives on lanes 0..3 of segment)
        h0 = __shfl_sync(FULLMASK, hu, 0, 16);
        h1 = __shfl_sync(FULLMASK, hu, 1, 16);
        h2 = __shfl_sync(FULLMASK, hu, 2, 16);
        h3 = __shfl_sync(FULLMASK, hu, 3, 16);
    }

    // hx, cx appended after outputs
    if (isStore) {
        size_t baseH = (size_t)T_STEPS * BATCH * 4;
        size_t baseC = baseH + (size_t)BATCH * 4;
        out[baseH + (size_t)b * 4 + u] = huK;
        out[baseC + (size_t)b * 4 + u] = c;
    }
}

// ---------------------------------------------------------------------------
extern "C" void kernel_launch(void* const* d_in, const int* in_sizes, int n_in,
                              void* d_out, int out_size)
{
    (void)in_sizes; (void)n_in; (void)out_size;
    const float* x   = (const float*)d_in[0];
    const float* Wf  = (const float*)d_in[1];
    const float* bf  = (const float*)d_in[2];
    const float* thf = (const float*)d_in[3];
    const float* Wi  = (const float*)d_in[4];
    const float* bi  = (const float*)d_in[5];
    const float* thi = (const float*)d_in[6];
    const float* Wu  = (const float*)d_in[7];
    const float* bu  = (const float*)d_in[8];
    const float* thu = (const float*)d_in[9];
    const float* Wo  = (const float*)d_in[10];
    const float* bo  = (const float*)d_in[11];
    const float* tho = (const float*)d_in[12];
    float* out = (float*)d_out;

    proj_kernel<<<(T_STEPS * BATCH) / TILE_ROWS, PROJ_THREADS>>>(
        x, Wf, bf, thf, Wi, bi, thi, Wu, bu, thu, Wo, bo, tho);
    recur_kernel<<<BATCH / 2, 32>>>(Wf, Wi, Wu, Wo, out);
}

// round 7
// speedup vs baseline: 2.0336x; 2.0336x over previous
#include <cuda_runtime.h>

#define T_STEPS 2048
#define BATCH   256
#define DIN     128
#define NG      16      // scratch layout k = u*4 + g
#define RDEPTH  4

// Scratch: x-part projections (+bias+theta folded), layout [t][b][u*4+g]
// Over-allocated by RDEPTH steps so the recurrence prefetch needs no bounds check.
__device__ float g_xproj[(T_STEPS + RDEPTH) * BATCH * NG];

// ---------------------------------------------------------------------------
// Kernel 1: fused 4-gate projection (identical to the 596us-best version)
// ---------------------------------------------------------------------------
#define TILE_ROWS    64
#define PROJ_THREADS 256

__global__ __launch_bounds__(PROJ_THREADS)
void proj_kernel(const float* __restrict__ x,
                 const float* __restrict__ Wf, const float* __restrict__ bf, const float* __restrict__ thf,
                 const float* __restrict__ Wi, const float* __restrict__ bi, const float* __restrict__ thi,
                 const float* __restrict__ Wu, const float* __restrict__ bu, const float* __restrict__ thu,
                 const float* __restrict__ Wo, const float* __restrict__ bo, const float* __restrict__ tho)
{
    __shared__ float xs[TILE_ROWS][132];
    __shared__ float ws[DIN][NG];          // ws[j][u*4+g]
    __shared__ float bt[NG];

    const int tid = threadIdx.x;
    const long rowBase = (long)blockIdx.x * TILE_ROWS;

    const float4* x4 = (const float4*)x + rowBase * (DIN / 4);
    #pragma unroll
    for (int i = tid; i < TILE_ROWS * (DIN / 4); i += PROJ_THREADS) {
        float4 v = x4[i];
        int row = i >> 5;
        int c4  = i & 31;
        *(float4*)&xs[row][c4 * 4] = v;
    }
    // stage W transposed: k = u*4 + g
    for (int i = tid; i < DIN * NG; i += PROJ_THREADS) {
        int j = i >> 4, k = i & 15;
        int u = k >> 2, g = k & 3;
        const float* W = (g == 0) ? Wf : (g == 1) ? Wi : (g == 2) ? Wu : Wo;
        ws[j][k] = W[j * 4 + u];
    }
    if (tid < NG) {
        int u = tid >> 2, g = tid & 3;
        const float* b  = (g == 0) ? bf  : (g == 1) ? bi  : (g == 2) ? bu  : bo;
        const float* th = (g == 0) ? thf : (g == 1) ? thi : (g == 2) ? thu : tho;
        bt[tid] = b[u] + th[u];
    }
    __syncthreads();

    const int r  = tid & (TILE_ROWS - 1);
    const int kg = tid >> 6;
    float a0 = 0.f, a1 = 0.f, a2 = 0.f, a3 = 0.f;

    #pragma unroll
    for (int jj = 0; jj < DIN / 4; jj++) {
        float4 xv = *(const float4*)&xs[r][jj * 4];
        float4 w0 = *(const float4*)&ws[jj * 4 + 0][kg * 4];
        float4 w1 = *(const float4*)&ws[jj * 4 + 1][kg * 4];
        float4 w2 = *(const float4*)&ws[jj * 4 + 2][kg * 4];
        float4 w3 = *(const float4*)&ws[jj * 4 + 3][kg * 4];
        a0 = fmaf(xv.x, w0.x, fmaf(xv.y, w1.x, fmaf(xv.z, w2.x, fmaf(xv.w, w3.x, a0))));
        a1 = fmaf(xv.x, w0.y, fmaf(xv.y, w1.y, fmaf(xv.z, w2.y, fmaf(xv.w, w3.y, a1))));
        a2 = fmaf(xv.x, w0.z, fmaf(xv.y, w1.z, fmaf(xv.z, w2.z, fmaf(xv.w, w3.z, a2))));
        a3 = fmaf(xv.x, w0.w, fmaf(xv.y, w1.w, fmaf(xv.z, w2.w, fmaf(xv.w, w3.w, a3))));
    }
    float4 o;
    o.x = a0 + bt[kg * 4 + 0];
    o.y = a1 + bt[kg * 4 + 1];
    o.z = a2 + bt[kg * 4 + 2];
    o.w = a3 + bt[kg * 4 + 3];
    *(float4*)&g_xproj[(rowBase + r) * NG + kg * 4] = o;
}

// ---------------------------------------------------------------------------
// Kernel 2: recurrence; 4 lanes per batch element (lane owns hidden unit u)
// ---------------------------------------------------------------------------
// HW tanh (MUFU.TANH), 1 instruction
__device__ __forceinline__ float tanh_a(float x) {
    float y;
    asm("tanh.approx.f32 %0, %1;" : "=f"(y) : "f"(x));
    return y;
}
// sigmoid via HW tanh: sig(x) = 0.5*tanh(x/2) + 0.5  (3 instr, 1 MUFU)
__device__ __forceinline__ float sig_t(float x) {
    return fmaf(0.5f, tanh_a(0.5f * x), 0.5f);
}

#define FULLMASK 0xffffffffu

__global__ __launch_bounds__(32)
void recur_kernel(const float* __restrict__ Wf, const float* __restrict__ Wi,
                  const float* __restrict__ Wu, const float* __restrict__ Wo,
                  float* __restrict__ out)
{
    const int lane = threadIdx.x;
    const int u    = lane & 3;                       // hidden unit owned by this lane
    const int b    = blockIdx.x * 8 + (lane >> 2);   // batch element of this 4-lane group

    // Whl[m][g] = W_gate_g[(128+m)*4 + u]
    float Whl[4][4];
    #pragma unroll
    for (int m = 0; m < 4; m++) {
        Whl[m][0] = Wf[(128 + m) * 4 + u];
        Whl[m][1] = Wi[(128 + m) * 4 + u];
        Whl[m][2] = Wu[(128 + m) * 4 + u];
        Whl[m][3] = Wo[(128 + m) * 4 + u];
    }
    const bool ge1 = (u >= 1);
    const bool ge2 = (u >= 2);

    float h0 = 0.f, h1 = 0.f, h2 = 0.f, h3 = 0.f;
    float c  = 0.f;

    const float4* xp = (const float4*)g_xproj + ((size_t)b * 4 + u);
    float4 buf[RDEPTH];
    #pragma unroll
    for (int d = 0; d < RDEPTH; d++)
        buf[d] = xp[(size_t)d * (BATCH * 4)];

    #pragma unroll 4
    for (int t = 0; t < T_STEPS; t++) {
        const int slot = t & (RDEPTH - 1);
        float4 zx = buf[slot];
        buf[slot] = xp[(size_t)(t + RDEPTH) * (BATCH * 4)];  // over-allocated: no bound check

        // z_g = zx_g + h . Whl[:,g]  (tree form) then cos
        float a, bb;
        a  = fmaf(h1, Whl[1][0], fmaf(h0, Whl[0][0], zx.x));
        bb = fmaf(h3, Whl[3][0], h2 * Whl[2][0]);
        float q0 = __cosf(a + bb);
        a  = fmaf(h1, Whl[1][1], fmaf(h0, Whl[0][1], zx.y));
        bb = fmaf(h3, Whl[3][1], h2 * Whl[2][1]);
        float q1 = __cosf(a + bb);
        a  = fmaf(h1, Whl[1][2], fmaf(h0, Whl[0][2], zx.z));
        bb = fmaf(h3, Whl[3][2], h2 * Whl[2][2]);
        float q2 = __cosf(a + bb);
        a  = fmaf(h1, Whl[1][3], fmaf(h0, Whl[0][3], zx.w));
        bb = fmaf(h3, Whl[3][3], h2 * Whl[2][3]);
        float q3 = __cosf(a + bb);

        // 2-round inclusive prefix product across the unit quad (width 4).
        // Tiny single-mult arms -> predicated FMUL (no divergence regions).
        {
            float v0 = __shfl_up_sync(FULLMASK, q0, 1, 4);
            float v1 = __shfl_up_sync(FULLMASK, q1, 1, 4);
            float v2 = __shfl_up_sync(FULLMASK, q2, 1, 4);
            float v3 = __shfl_up_sync(FULLMASK, q3, 1, 4);
            if (ge1) q0 *= v0;
            if (ge1) q1 *= v1;
            if (ge1) q2 *= v2;
            if (ge1) q3 *= v3;
            v0 = __shfl_up_sync(FULLMASK, q0, 2, 4);
            v1 = __shfl_up_sync(FULLMASK, q1, 2, 4);
            v2 = __shfl_up_sync(FULLMASK, q2, 2, 4);
            v3 = __shfl_up_sync(FULLMASK, q3, 2, 4);
            if (ge2) q0 *= v0;
            if (ge2) q1 *= v1;
            if (ge2) q2 *= v2;
            if (ge2) q3 *= v3;
        }

        // activations (all lane-local, uniform instruction stream)
        float f  = sig_t(q0);
        float i  = sig_t(q1);
        float gg = tanh_a(q2);
        float o  = sig_t(q3);

        c = fmaf(f, c, i * gg);
        float hu = o * tanh_a(c);

        out[((size_t)t * BATCH + b) * 4 + u] = hu;

        // broadcast h within the 4-lane group (4 parallel shfls)
        h0 = __shfl_sync(FULLMASK, hu, 0, 4);
        h1 = __shfl_sync(FULLMASK, hu, 1, 4);
        h2 = __shfl_sync(FULLMASK, hu, 2, 4);
        h3 = __shfl_sync(FULLMASK, hu, 3, 4);
    }

    // hx, cx appended after outputs
    float hx = (u == 0) ? h0 : (u == 1) ? h1 : (u == 2) ? h2 : h3;
    out[(size_t)T_STEPS * BATCH * 4 + (size_t)b * 4 + u]                     = hx;
    out[(size_t)T_STEPS * BATCH * 4 + (size_t)BATCH * 4 + (size_t)b * 4 + u] = c;
}

// ---------------------------------------------------------------------------
extern "C" void kernel_launch(void* const* d_in, const int* in_sizes, int n_in,
                              void* d_out, int out_size)
{
    (void)in_sizes; (void)n_in; (void)out_size;
    const float* x   = (const float*)d_in[0];
    const float* Wf  = (const float*)d_in[1];
    const float* bf  = (const float*)d_in[2];
    const float* thf = (const float*)d_in[3];
    const float* Wi  = (const float*)d_in[4];
    const float* bi  = (const float*)d_in[5];
    const float* thi = (const float*)d_in[6];
    const float* Wu  = (const float*)d_in[7];
    const float* bu  = (const float*)d_in[8];
    const float* thu = (const float*)d_in[9];
    const float* Wo  = (const float*)d_in[10];
    const float* bo  = (const float*)d_in[11];
    const float* tho = (const float*)d_in[12];
    float* out = (float*)d_out;

    proj_kernel<<<(T_STEPS * BATCH) / TILE_ROWS, PROJ_THREADS>>>(
        x, Wf, bf, thf, Wi, bi, thi, Wu, bu, thu, Wo, bo, tho);
    recur_kernel<<<BATCH / 8, 32>>>(Wf, Wi, Wu, Wo, out);
}